// round 13
// baseline (speedup 1.0000x reference)
#include <cuda_runtime.h>
#include <cuda_bf16.h>
#include <cstdint>

#define NODES 50000
#define MPAD  50176          // 392 * 128
#define EDIM  128
#define PDIM  768
#define HID   256
#define NREL  16
#define NEDGE 400000
#define BN_EPS 1e-5f
#define MBLK  392            // MPAD / 128
#define SCANB 196
#define PADR  (MPAD - NODES) // 176

// ---------------------------------------------------------------------------
// scratch (static device memory; no allocations)
// ---------------------------------------------------------------------------
__device__ __nv_bfloat16 g_Ah0[(size_t)MPAD * HID];
__device__ __nv_bfloat16 g_Al0[(size_t)MPAD * HID];
__device__ __nv_bfloat16 g_Ah1[(size_t)MPAD * HID];
__device__ __nv_bfloat16 g_Al1[(size_t)MPAD * HID];
__device__ __nv_bfloat16 g_Bth[3 * 256 * 768];
__device__ __nv_bfloat16 g_Btl[3 * 256 * 768];
__device__ float g_fbias[3 * HID];
__device__ float g_h0[(size_t)MPAD * HID];
__device__ float g_h1[(size_t)MPAD * HID];
__device__ float g_buf[(size_t)MPAD * HID];
__device__ int   g_cnt[NODES * NREL];
__device__ int   g_cntnode[NODES];
__device__ int   g_fill[NODES];
__device__ int   g_rowptr[NODES + 1];
__device__ int   g_blksum[SCANB];
__device__ int   g_packed[NEDGE];
__device__ float g_invw[NEDGE];
__device__ float g_sum[HID], g_sumsq[HID], g_scale[HID], g_shift[HID];

// ---------------------------------------------------------------------------
// helpers
// ---------------------------------------------------------------------------
__device__ __forceinline__ uint32_t smem_u32(const void* p) {
    uint32_t a;
    asm("{ .reg .u64 t; cvta.to.shared.u64 t, %1; cvt.u32.u64 %0, t; }" : "=r"(a) : "l"(p));
    return a;
}
__device__ __forceinline__ void cp16(uint32_t dst, const void* src) {
    asm volatile("cp.async.cg.shared.global [%0], [%1], 16;" :: "r"(dst), "l"(src) : "memory");
}
__device__ __forceinline__ void ldsm4(uint32_t* r, uint32_t addr) {
    asm volatile("ldmatrix.sync.aligned.m8n8.x4.shared.b16 {%0,%1,%2,%3}, [%4];"
                 : "=r"(r[0]), "=r"(r[1]), "=r"(r[2]), "=r"(r[3]) : "r"(addr));
}
__device__ __forceinline__ void mma16816(float* c, const uint32_t* a, const uint32_t* b) {
    asm volatile("mma.sync.aligned.m16n8k16.row.col.f32.bf16.bf16.f32 "
                 "{%0,%1,%2,%3}, {%4,%5,%6,%7}, {%8,%9}, {%0,%1,%2,%3};"
                 : "+f"(c[0]), "+f"(c[1]), "+f"(c[2]), "+f"(c[3])
                 : "r"(a[0]), "r"(a[1]), "r"(a[2]), "r"(a[3]), "r"(b[0]), "r"(b[1]));
}
static __device__ __forceinline__ uint32_t pack_bf2(float a, float b) {
    __nv_bfloat162 t;
    t.x = __float2bfloat16_rn(a);
    t.y = __float2bfloat16_rn(b);
    return *reinterpret_cast<uint32_t*>(&t);
}

// chunk-32 layout: 64B rows padded to 80B. A tile 128 rows, B tile 256 rows.
#define ROWB    80
#define A_MAT   10240          // 128*80
#define B_MAT   20480          // 256*80
#define B_BASE  20480          // 2*A_MAT
#define STAGEB  61440          // 2*A_MAT + 2*B_MAT
#define SMEM_GEMM (2 * STAGEB) // 122880 -> 1 CTA/SM

// ---------------------------------------------------------------------------
// split-bf16 GEMM via mma.sync: C_z = A @ B_z^T (+bias_z)
// CTA tile 128x256 (full N), 256 threads (2x4 warps), WARP TILE 64x64,
// K-chunk 32, 2-stage cp.async. 85 B smem per MMA (vs 128 before).
// blockIdx.x = z (weight matrix), blockIdx.y = row block.
// ---------------------------------------------------------------------------
__device__ __forceinline__ void load_stage(
    uint32_t sb, int stage, int k0,
    const __nv_bfloat16* __restrict__ Ah, const __nv_bfloat16* __restrict__ Al,
    const __nv_bfloat16* __restrict__ Bh, const __nv_bfloat16* __restrict__ Bl,
    int K, int t)
{
    uint32_t base = sb + stage * STAGEB;
#pragma unroll
    for (int i = 0; i < 2; i++) {          // A: 128 rows x 4 units, h+l
        int unit = t + i * 256;
        int r = unit >> 2, u = unit & 3;
        uint32_t off = r * ROWB + u * 16;
        cp16(base + off,         Ah + (size_t)r * K + k0 + u * 8);
        cp16(base + A_MAT + off, Al + (size_t)r * K + k0 + u * 8);
    }
#pragma unroll
    for (int i = 0; i < 4; i++) {          // B: 256 rows x 4 units, h+l
        int unit = t + i * 256;
        int r = unit >> 2, u = unit & 3;
        uint32_t off = r * ROWB + u * 16;
        cp16(base + B_BASE + off,         Bh + (size_t)r * K + k0 + u * 8);
        cp16(base + B_BASE + B_MAT + off, Bl + (size_t)r * K + k0 + u * 8);
    }
    asm volatile("cp.async.commit_group;" ::: "memory");
}

__global__ void __launch_bounds__(256, 1) gemm_mma(
    const __nv_bfloat16* __restrict__ Ah, const __nv_bfloat16* __restrict__ Al,
    int K,
    const __nv_bfloat16* __restrict__ Bth, const __nv_bfloat16* __restrict__ Btl,
    float* C0, float* C1, float* C2, int ldc,
    const float* bias0, const float* bias1, const float* bias2)
{
    extern __shared__ char smem[];
    uint32_t sb = smem_u32(smem);
    const int t = threadIdx.x;
    const int w = t >> 5, l = t & 31;
    const int wm = w >> 2, wn = w & 3;     // 2 x 4 warps, warp tile 64x64
    const int z = blockIdx.x;
    const int row0 = blockIdx.y * 128;

    float* C = (z == 0) ? C0 : (z == 1) ? C1 : C2;
    const float* bias = (z == 0) ? bias0 : (z == 1) ? bias1 : bias2;

    const __nv_bfloat16* A_h = Ah + (size_t)row0 * K;
    const __nv_bfloat16* A_l = Al + (size_t)row0 * K;
    size_t Boff = (size_t)z * 256 * K;
    const __nv_bfloat16* B_h = Bth + Boff;
    const __nv_bfloat16* B_l = Btl + Boff;

    const uint32_t aoff = (uint32_t)((wm * 64 + (l & 15)) * ROWB + (l >> 4) * 16);
    const uint32_t boff = (uint32_t)((wn * 64 + (l & 7) + ((l >> 4) & 1) * 8) * ROWB
                                     + ((l >> 3) & 1) * 16);

    float acc[4][8][4];
#pragma unroll
    for (int mt = 0; mt < 4; mt++)
#pragma unroll
        for (int nt = 0; nt < 8; nt++)
#pragma unroll
            for (int j = 0; j < 4; j++) acc[mt][nt][j] = 0.f;

    const int nch = K >> 5;
    load_stage(sb, 0, 0, A_h, A_l, B_h, B_l, K, t);

    for (int c = 0; c < nch; c++) {
        if (c + 1 < nch) {
            load_stage(sb, (c + 1) & 1, (c + 1) << 5, A_h, A_l, B_h, B_l, K, t);
            asm volatile("cp.async.wait_group 1;" ::: "memory");
        } else {
            asm volatile("cp.async.wait_group 0;" ::: "memory");
        }
        __syncthreads();

        uint32_t Abase = sb + (c & 1) * STAGEB;
        uint32_t Bbase = Abase + B_BASE;
#pragma unroll
        for (int ks = 0; ks < 2; ks++) {
            uint32_t bh[4][4], bl[4][4];
#pragma unroll
            for (int p = 0; p < 4; p++) {
                ldsm4(bh[p], Bbase + boff + p * 1280 + ks * 32);
                ldsm4(bl[p], Bbase + B_MAT + boff + p * 1280 + ks * 32);
            }
#pragma unroll
            for (int mt = 0; mt < 4; mt++) {
                uint32_t ah[4], al[4];
                ldsm4(ah, Abase + aoff + mt * 1280 + ks * 32);
                ldsm4(al, Abase + A_MAT + aoff + mt * 1280 + ks * 32);
#pragma unroll
                for (int nt = 0; nt < 8; nt++) {
                    float* cc = acc[mt][nt];
                    const uint32_t* bph = &bh[nt >> 1][(nt & 1) * 2];
                    const uint32_t* bpl = &bl[nt >> 1][(nt & 1) * 2];
                    mma16816(cc, ah, bph);
                    mma16816(cc, al, bph);
                    mma16816(cc, ah, bpl);
                }
            }
        }
        __syncthreads();
    }

    const int rl = l >> 2;
    const int cl = (l & 3) * 2;
#pragma unroll
    for (int mt = 0; mt < 4; mt++) {
#pragma unroll
        for (int rh = 0; rh < 2; rh++) {
            int r = row0 + wm * 64 + mt * 16 + rh * 8 + rl;
#pragma unroll
            for (int nt = 0; nt < 8; nt++) {
                int cix = wn * 64 + nt * 8 + cl;
                float v0 = acc[mt][nt][rh * 2 + 0];
                float v1 = acc[mt][nt][rh * 2 + 1];
                if (bias) { v0 += bias[cix]; v1 += bias[cix + 1]; }
                *(float2*)(C + (size_t)r * ldc + cix) = make_float2(v0, v1);
            }
        }
    }
}

// ---------------------------------------------------------------------------
// producers
// ---------------------------------------------------------------------------
__global__ void norm_split(const float* __restrict__ emb,
                           __nv_bfloat16* __restrict__ Ah, __nv_bfloat16* __restrict__ Al) {
    int gw = (blockIdx.x * blockDim.x + threadIdx.x) >> 5;
    if (gw >= NODES) return;
    int lane = threadIdx.x & 31;
    float4 v = ((const float4*)(emb + (size_t)gw * EDIM))[lane];
    float ss = v.x * v.x + v.y * v.y + v.z * v.z + v.w * v.w;
#pragma unroll
    for (int o = 16; o > 0; o >>= 1) ss += __shfl_xor_sync(0xffffffffu, ss, o);
    float inv = 1.0f / fmaxf(sqrtf(ss), 1e-12f);
    v.x *= inv; v.y *= inv; v.z *= inv; v.w *= inv;
    __nv_bfloat16 hx = __float2bfloat16_rn(v.x), hy = __float2bfloat16_rn(v.y);
    __nv_bfloat16 hz = __float2bfloat16_rn(v.z), hw = __float2bfloat16_rn(v.w);
    size_t ui = ((size_t)gw * EDIM + lane * 4) >> 1;
    __nv_bfloat162 p0; p0.x = hx; p0.y = hy;
    __nv_bfloat162 p1; p1.x = hz; p1.y = hw;
    ((uint32_t*)Ah)[ui]     = *reinterpret_cast<uint32_t*>(&p0);
    ((uint32_t*)Ah)[ui + 1] = *reinterpret_cast<uint32_t*>(&p1);
    ((uint32_t*)Al)[ui]     = pack_bf2(v.x - __bfloat162float(hx), v.y - __bfloat162float(hy));
    ((uint32_t*)Al)[ui + 1] = pack_bf2(v.z - __bfloat162float(hz), v.w - __bfloat162float(hw));
}

__global__ void zero_pads_all() {
    const int Ks[3] = {128, 256, 256};
    int reg = blockIdx.y;
    int K = Ks[reg];
    int n = PADR * K / 2;
    int i = blockIdx.x * blockDim.x + threadIdx.x;
    if (i >= n) return;
    size_t base = (size_t)NODES * K / 2;
    if (reg < 2) {
        ((uint32_t*)g_Ah0)[base + i] = 0;
        ((uint32_t*)g_Al0)[base + i] = 0;
    } else {
        ((uint32_t*)g_Ah1)[base + i] = 0;
        ((uint32_t*)g_Al1)[base + i] = 0;
    }
}

__global__ void fuse_w(const float* __restrict__ proj_w, const float* __restrict__ proj_b,
                       const float* __restrict__ bases0, const float* __restrict__ root0,
                       const float* __restrict__ bias0) {
    int z = blockIdx.y;
    int idx = blockIdx.x * blockDim.x + threadIdx.x;
    if (idx >= EDIM * HID) return;
    int e = idx >> 8, o = idx & 255;
    const float* W = (z < 2) ? bases0 + (size_t)z * PDIM * HID : root0;
    const float* pw = proj_w + (size_t)e * PDIM;
    float s0 = 0.f, s1 = 0.f, s2 = 0.f, s3 = 0.f;
    for (int p = 0; p < PDIM; p += 4) {
        s0 = fmaf(pw[p + 0], W[(size_t)(p + 0) * HID + o], s0);
        s1 = fmaf(pw[p + 1], W[(size_t)(p + 1) * HID + o], s1);
        s2 = fmaf(pw[p + 2], W[(size_t)(p + 2) * HID + o], s2);
        s3 = fmaf(pw[p + 3], W[(size_t)(p + 3) * HID + o], s3);
    }
    float s = (s0 + s1) + (s2 + s3);
    __nv_bfloat16 h = __float2bfloat16_rn(s);
    size_t off = ((size_t)(z * HID + o)) * EDIM + e;
    g_Bth[off] = h;
    g_Btl[off] = __float2bfloat16_rn(s - __bfloat162float(h));
    if (e == 0) {
        float b = 0.f;
        for (int p = 0; p < PDIM; p++) b = fmaf(proj_b[p], W[(size_t)p * HID + o], b);
        if (z == 2) b += bias0[o];
        g_fbias[z * HID + o] = b;
    }
}

__global__ void split_bt_layer(const float* __restrict__ bases, const float* __restrict__ root, int K) {
    int z = blockIdx.z;
    int idx = blockIdx.x * blockDim.x + threadIdx.x;
    const float* in = (z < 2) ? bases + (size_t)z * K * HID : root;
    if (idx >= K * HID) return;
    int k = idx / HID, n = idx % HID;
    float v = in[idx];
    __nv_bfloat16 h = __float2bfloat16_rn(v);
    size_t o = ((size_t)z * HID + n) * K + k;
    g_Bth[o] = h;
    g_Btl[o] = __float2bfloat16_rn(v - __bfloat162float(h));
}

// ---------------------------------------------------------------------------
// CSR build
// ---------------------------------------------------------------------------
__global__ void zero_counts() {
    int i = blockIdx.x * blockDim.x + threadIdx.x;
    if (i < NODES * NREL) g_cnt[i] = 0;
    if (i < NODES) { g_cntnode[i] = 0; g_fill[i] = 0; }
}
__global__ void count_edges(const int* __restrict__ dst, const int* __restrict__ et) {
    int e = blockIdx.x * blockDim.x + threadIdx.x;
    if (e < NEDGE) {
        int d = dst[e];
        atomicAdd(&g_cnt[d * NREL + et[e]], 1);
        atomicAdd(&g_cntnode[d], 1);
    }
}
__global__ void scan1() {
    __shared__ int sh[256];
    int t = threadIdx.x;
    int idx = blockIdx.x * 256 + t;
    int v = (idx < NODES) ? g_cntnode[idx] : 0;
    sh[t] = v;
    __syncthreads();
#pragma unroll
    for (int o = 1; o < 256; o <<= 1) {
        int x = (t >= o) ? sh[t - o] : 0;
        __syncthreads();
        sh[t] += x;
        __syncthreads();
    }
    if (idx < NODES) g_rowptr[idx + 1] = sh[t];
    if (t == 255) g_blksum[blockIdx.x] = sh[255];
}
__global__ void scan2() {
    int t = threadIdx.x;
    int carry = 0;
    for (int base = 0; base < SCANB; base += 32) {
        int idx = base + t;
        int vin = (idx < SCANB) ? g_blksum[idx] : 0;
        int v = vin;
#pragma unroll
        for (int o = 1; o < 32; o <<= 1) {
            int x = __shfl_up_sync(0xffffffffu, v, o);
            if (t >= o) v += x;
        }
        if (idx < SCANB) g_blksum[idx] = carry + v - vin;
        carry += __shfl_sync(0xffffffffu, v, 31);
    }
    if (t == 0) g_rowptr[0] = 0;
}
__global__ void scan3() {
    int idx = blockIdx.x * blockDim.x + threadIdx.x;
    if (idx < NODES) g_rowptr[idx + 1] += g_blksum[idx >> 8];
}
__global__ void scatter_edges(const int* __restrict__ src, const int* __restrict__ dst,
                              const int* __restrict__ et) {
    int e = blockIdx.x * blockDim.x + threadIdx.x;
    if (e >= NEDGE) return;
    int d = dst[e], r = et[e], s = src[e];
    int pos = g_rowptr[d] + atomicAdd(&g_fill[d], 1);
    g_packed[pos] = s | (r << 24);
    int c = g_cnt[d * NREL + r];
    g_invw[pos] = 1.0f / (float)(c > 0 ? c : 1);
}

// ---------------------------------------------------------------------------
// gather aggregation + fused BN statistics (zeroes stats itself via block 0)
// ---------------------------------------------------------------------------
#define AGG_BLOCKS 1184
__global__ void __launch_bounds__(256) csr_agg_bn(const float* __restrict__ comp) {
    __shared__ float s_sum[HID];
    __shared__ float s_sumsq[HID];
    __shared__ float s_comp[2 * NREL];
    int t = threadIdx.x;
    if (t < 2 * NREL) s_comp[t] = comp[t];
    s_sum[t] = 0.f;
    s_sumsq[t] = 0.f;
    __syncthreads();

    int lane = t & 31, wid = t >> 5;
    float bsum[8], bsq[8];
#pragma unroll
    for (int i = 0; i < 8; i++) { bsum[i] = 0.f; bsq[i] = 0.f; }

    for (int d = blockIdx.x * 8 + wid; d < NODES; d += AGG_BLOCKS * 8) {
        int beg = g_rowptr[d], end = g_rowptr[d + 1];
        float* bp = &g_buf[(size_t)d * HID];
        float4 acc0 = ((float4*)bp)[lane];
        float4 acc1 = ((float4*)bp)[lane + 32];
        for (int e = beg; e < end; e++) {
            int pk = __ldg(&g_packed[e]);
            float w = __ldg(&g_invw[e]);
            int s = pk & 0xFFFFFF;
            int r = pk >> 24;
            float c0 = s_comp[2 * r] * w;
            float c1 = s_comp[2 * r + 1] * w;
            const float4* h0p = (const float4*)&g_h0[(size_t)s * HID];
            const float4* h1p = (const float4*)&g_h1[(size_t)s * HID];
            float4 a0 = h0p[lane],      b0 = h1p[lane];
            float4 a1 = h0p[lane + 32], b1 = h1p[lane + 32];
            acc0.x += c0 * a0.x + c1 * b0.x;
            acc0.y += c0 * a0.y + c1 * b0.y;
            acc0.z += c0 * a0.z + c1 * b0.z;
            acc0.w += c0 * a0.w + c1 * b0.w;
            acc1.x += c0 * a1.x + c1 * b1.x;
            acc1.y += c0 * a1.y + c1 * b1.y;
            acc1.z += c0 * a1.z + c1 * b1.z;
            acc1.w += c0 * a1.w + c1 * b1.w;
        }
        ((float4*)bp)[lane] = acc0;
        ((float4*)bp)[lane + 32] = acc1;
        bsum[0] += acc0.x; bsq[0] += acc0.x * acc0.x;
        bsum[1] += acc0.y; bsq[1] += acc0.y * acc0.y;
        bsum[2] += acc0.z; bsq[2] += acc0.z * acc0.z;
        bsum[3] += acc0.w; bsq[3] += acc0.w * acc0.w;
        bsum[4] += acc1.x; bsq[4] += acc1.x * acc1.x;
        bsum[5] += acc1.y; bsq[5] += acc1.y * acc1.y;
        bsum[6] += acc1.z; bsq[6] += acc1.z * acc1.z;
        bsum[7] += acc1.w; bsq[7] += acc1.w * acc1.w;
    }

#pragma unroll
    for (int i = 0; i < 4; i++) {
        atomicAdd(&s_sum[lane * 4 + i], bsum[i]);
        atomicAdd(&s_sumsq[lane * 4 + i], bsq[i]);
        atomicAdd(&s_sum[128 + lane * 4 + i], bsum[4 + i]);
        atomicAdd(&s_sumsq[128 + lane * 4 + i], bsq[4 + i]);
    }
    __syncthreads();
    atomicAdd(&g_sum[t], s_sum[t]);
    atomicAdd(&g_sumsq[t], s_sumsq[t]);
}

__global__ void zero_stats() {
    int c = threadIdx.x;
    g_sum[c] = 0.f;
    g_sumsq[c] = 0.f;
}

// ---------------------------------------------------------------------------
// batchnorm finalize + apply (round-10 proven structure)
// ---------------------------------------------------------------------------
__global__ void bn_finalize(const float* __restrict__ gamma, const float* __restrict__ beta) {
    int c = threadIdx.x;
    const float invM = 1.0f / (float)NODES;
    float mean = g_sum[c] * invM;
    float var = g_sumsq[c] * invM - mean * mean;
    float sc = gamma[c] * rsqrtf(var + BN_EPS);
    g_scale[c] = sc;
    g_shift[c] = beta[c] - mean * sc;
}
__global__ void bn_apply_f32(float* __restrict__ out) {
    int idx = blockIdx.x * blockDim.x + threadIdx.x;
    if (idx >= NODES * HID / 4) return;
    int c4 = (idx & 63) << 2;
    float4 v = ((const float4*)g_buf)[idx];
    float4 sc = *(const float4*)&g_scale[c4];
    float4 sh = *(const float4*)&g_shift[c4];
    v.x = fmaxf(fmaf(v.x, sc.x, sh.x), 0.f);
    v.y = fmaxf(fmaf(v.y, sc.y, sh.y), 0.f);
    v.z = fmaxf(fmaf(v.z, sc.z, sh.z), 0.f);
    v.w = fmaxf(fmaf(v.w, sc.w, sh.w), 0.f);
    ((float4*)out)[idx] = v;
}
__global__ void bn_apply_split(__nv_bfloat16* __restrict__ Ah, __nv_bfloat16* __restrict__ Al) {
    int idx = blockIdx.x * blockDim.x + threadIdx.x;
    if (idx >= NODES * HID / 4) return;
    int c4 = (idx & 63) << 2;
    float4 v = ((const float4*)g_buf)[idx];
    float4 sc = *(const float4*)&g_scale[c4];
    float4 sh = *(const float4*)&g_shift[c4];
    v.x = fmaxf(fmaf(v.x, sc.x, sh.x), 0.f);
    v.y = fmaxf(fmaf(v.y, sc.y, sh.y), 0.f);
    v.z = fmaxf(fmaf(v.z, sc.z, sh.z), 0.f);
    v.w = fmaxf(fmaf(v.w, sc.w, sh.w), 0.f);
    __nv_bfloat16 hx = __float2bfloat16_rn(v.x), hy = __float2bfloat16_rn(v.y);
    __nv_bfloat16 hz = __float2bfloat16_rn(v.z), hw = __float2bfloat16_rn(v.w);
    __nv_bfloat162 p0; p0.x = hx; p0.y = hy;
    __nv_bfloat162 p1; p1.x = hz; p1.y = hw;
    ((uint32_t*)Ah)[idx * 2]     = *reinterpret_cast<uint32_t*>(&p0);
    ((uint32_t*)Ah)[idx * 2 + 1] = *reinterpret_cast<uint32_t*>(&p1);
    ((uint32_t*)Al)[idx * 2]     = pack_bf2(v.x - __bfloat162float(hx), v.y - __bfloat162float(hy));
    ((uint32_t*)Al)[idx * 2 + 1] = pack_bf2(v.z - __bfloat162float(hz), v.w - __bfloat162float(hw));
}

// ---------------------------------------------------------------------------
// host launch
// ---------------------------------------------------------------------------
extern "C" void kernel_launch(void* const* d_in, const int* in_sizes, int n_in,
                              void* d_out, int out_size) {
    const int* edge_index = (const int*)d_in[0];
    const int* src = edge_index;
    const int* dst = edge_index + NEDGE;
    const int* etype = (const int*)d_in[1];
    const float* emb = (const float*)d_in[2];
    const float* proj_w = (const float*)d_in[3];
    const float* proj_b = (const float*)d_in[4];

    const float *comp[3], *bases[3], *root[3], *bias[3], *gamma[3], *beta[3];
    for (int l = 0; l < 3; l++) {
        comp[l]  = (const float*)d_in[5 + 6 * l];
        bases[l] = (const float*)d_in[6 + 6 * l];
        root[l]  = (const float*)d_in[7 + 6 * l];
        bias[l]  = (const float*)d_in[8 + 6 * l];
        gamma[l] = (const float*)d_in[9 + 6 * l];
        beta[l]  = (const float*)d_in[10 + 6 * l];
    }

    __nv_bfloat16 *Ah0, *Al0, *Ah1, *Al1, *Bth, *Btl;
    float *h0, *h1, *buf, *fbias;
    cudaGetSymbolAddress((void**)&Ah0, g_Ah0);
    cudaGetSymbolAddress((void**)&Al0, g_Al0);
    cudaGetSymbolAddress((void**)&Ah1, g_Ah1);
    cudaGetSymbolAddress((void**)&Al1, g_Al1);
    cudaGetSymbolAddress((void**)&Bth, g_Bth);
    cudaGetSymbolAddress((void**)&Btl, g_Btl);
    cudaGetSymbolAddress((void**)&h0, g_h0);
    cudaGetSymbolAddress((void**)&h1, g_h1);
    cudaGetSymbolAddress((void**)&buf, g_buf);
    cudaGetSymbolAddress((void**)&fbias, g_fbias);

    cudaFuncSetAttribute(gemm_mma, cudaFuncAttributeMaxDynamicSharedMemorySize, SMEM_GEMM);

    // producers
    norm_split<<<(NODES * 32 + 255) / 256, 256>>>(emb, Ah0, Al0);
    {
        dim3 g((PADR * 256 / 2 + 255) / 256, 3);
        zero_pads_all<<<g, 256>>>();
    }
    {
        dim3 g((EDIM * HID + 255) / 256, 3);
        fuse_w<<<g, 256>>>(proj_w, proj_b, bases[0], root[0], bias[0]);
    }

    // launch 4: layer0 GEMM (ncu capture target), K=128
    {
        dim3 grid(3, MBLK);
        gemm_mma<<<grid, 256, SMEM_GEMM>>>(
            Ah0, Al0, EDIM, Bth, Btl,
            h0, h1, buf, HID,
            fbias, fbias + HID, fbias + 2 * HID);
    }

    // CSR build
    zero_counts<<<(NODES * NREL + 255) / 256, 256>>>();
    count_edges<<<(NEDGE + 255) / 256, 256>>>(dst, etype);
    scan1<<<SCANB, 256>>>();
    scan2<<<1, 32>>>();
    scan3<<<(NODES + 255) / 256, 256>>>();
    scatter_edges<<<(NEDGE + 255) / 256, 256>>>(src, dst, etype);

    for (int l = 0; l < 3; l++) {
        if (l > 0) {
            dim3 g((HID * HID + 255) / 256, 1, 3);
            split_bt_layer<<<g, 256>>>(bases[l], root[l], HID);
            __nv_bfloat16* Ah = (l == 1) ? Ah1 : Ah0;
            __nv_bfloat16* Al = (l == 1) ? Al1 : Al0;
            dim3 grid(3, MBLK);
            gemm_mma<<<grid, 256, SMEM_GEMM>>>(
                Ah, Al, HID, Bth, Btl,
                h0, h1, buf, HID,
                nullptr, nullptr, bias[l]);
        }
        zero_stats<<<1, HID>>>();
        csr_agg_bn<<<AGG_BLOCKS, 256>>>(comp[l]);
        bn_finalize<<<1, HID>>>(gamma[l], beta[l]);
        if (l < 2) {
            __nv_bfloat16* oAh = (l == 0) ? Ah1 : Ah0;
            __nv_bfloat16* oAl = (l == 0) ? Al1 : Al0;
            bn_apply_split<<<(NODES * HID / 4 + 255) / 256, 256>>>(oAh, oAl);
        } else {
            bn_apply_f32<<<(NODES * HID / 4 + 255) / 256, 256>>>((float*)d_out);
        }
    }
}

// round 14
// speedup vs baseline: 1.2112x; 1.2112x over previous
#include <cuda_runtime.h>
#include <cuda_fp16.h>
#include <cstdint>

#define NODES 50000
#define MPAD  50176          // 392 * 128
#define EDIM  128
#define PDIM  768
#define HID   256
#define NREL  16
#define NEDGE 400000
#define BN_EPS 1e-5f
#define MBLK  392            // MPAD / 128
#define SCANB 196
#define PADR  (MPAD - NODES)

// ---------------------------------------------------------------------------
// scratch (static device memory; no allocations)
// ---------------------------------------------------------------------------
__device__ __half g_A0[(size_t)MPAD * HID];     // x (fp16): layer0 xn K=128, layer2 input K=256
__device__ __half g_A1[(size_t)MPAD * HID];     // layer1 input K=256
__device__ __half g_Bth[3 * 256 * 768];          // B^T hi (K-major)
__device__ __half g_Btl[3 * 256 * 768];          // B^T lo
__device__ float g_fbias[3 * HID];
__device__ float g_h0[(size_t)MPAD * HID];
__device__ float g_h1[(size_t)MPAD * HID];
__device__ float g_buf[(size_t)MPAD * HID];
__device__ int   g_cnt[NODES * NREL];
__device__ int   g_cntnode[NODES];
__device__ int   g_fill[NODES];
__device__ int   g_rowptr[NODES + 1];
__device__ int   g_blksum[SCANB];
__device__ int   g_packed[NEDGE];
__device__ float g_invw[NEDGE];
__device__ float g_sum[HID], g_sumsq[HID], g_scale[HID], g_shift[HID];

// ---------------------------------------------------------------------------
// helpers
// ---------------------------------------------------------------------------
__device__ __forceinline__ uint32_t smem_u32(const void* p) {
    uint32_t a;
    asm("{ .reg .u64 t; cvta.to.shared.u64 t, %1; cvt.u32.u64 %0, t; }" : "=r"(a) : "l"(p));
    return a;
}
__device__ __forceinline__ void cp16(uint32_t dst, const void* src) {
    asm volatile("cp.async.cg.shared.global [%0], [%1], 16;" :: "r"(dst), "l"(src) : "memory");
}
__device__ __forceinline__ void ldsm4(uint32_t* r, uint32_t addr) {
    asm volatile("ldmatrix.sync.aligned.m8n8.x4.shared.b16 {%0,%1,%2,%3}, [%4];"
                 : "=r"(r[0]), "=r"(r[1]), "=r"(r[2]), "=r"(r[3]) : "r"(addr));
}
__device__ __forceinline__ void mma16816(float* c, const uint32_t* a, const uint32_t* b) {
    asm volatile("mma.sync.aligned.m16n8k16.row.col.f32.f16.f16.f32 "
                 "{%0,%1,%2,%3}, {%4,%5,%6,%7}, {%8,%9}, {%0,%1,%2,%3};"
                 : "+f"(c[0]), "+f"(c[1]), "+f"(c[2]), "+f"(c[3])
                 : "r"(a[0]), "r"(a[1]), "r"(a[2]), "r"(a[3]), "r"(b[0]), "r"(b[1]));
}
static __device__ __forceinline__ uint32_t pack_h2(float a, float b) {
    __half2 t;
    t.x = __float2half_rn(a);
    t.y = __float2half_rn(b);
    return *reinterpret_cast<uint32_t*>(&t);
}

// chunk-32 layout: 64B rows padded to 80B. stage = A(128x80) | Bh(128x80) | Bl(128x80)
#define ROWB    80
#define A_MAT   10240
#define STAGEB  30720
#define SMEM_GEMM (2 * STAGEB)   // 61440 -> 2 CTAs/SM

// ---------------------------------------------------------------------------
// fp16 2-term GEMM via mma.sync: C = A @ (Bh+Bl)^T (+bias)
// CTA tile 128x128, 256 threads (2x4 warps), warp tile 64x32, K-chunk 32,
// 2-stage cp.async, 2 CTAs/SM. blockIdx.x = output tile (A reuse), .y = rows.
// ---------------------------------------------------------------------------
__device__ __forceinline__ void load_stage(
    uint32_t sb, int stage, int k0,
    const __half* __restrict__ A,
    const __half* __restrict__ Bh, const __half* __restrict__ Bl,
    int K, int t)
{
    uint32_t base = sb + stage * STAGEB;
#pragma unroll
    for (int i = 0; i < 2; i++) {
        int unit = t + i * 256;
        int r = unit >> 2, u = unit & 3;
        uint32_t off = r * ROWB + u * 16;
        cp16(base + off, A + (size_t)r * K + k0 + u * 8);
    }
#pragma unroll
    for (int i = 0; i < 2; i++) {
        int unit = t + i * 256;
        int r = unit >> 2, u = unit & 3;
        uint32_t off = r * ROWB + u * 16;
        cp16(base + A_MAT + off,     Bh + (size_t)r * K + k0 + u * 8);
        cp16(base + 2 * A_MAT + off, Bl + (size_t)r * K + k0 + u * 8);
    }
    asm volatile("cp.async.commit_group;" ::: "memory");
}

__global__ void __launch_bounds__(256, 2) gemm_mma(
    const __half* __restrict__ A, int K, int nbz,
    const __half* __restrict__ Bth, const __half* __restrict__ Btl,
    float* C0, float* C1, float* C2, int ldc,
    const float* bias0, const float* bias1, const float* bias2)
{
    extern __shared__ char smem[];
    uint32_t sb = smem_u32(smem);
    const int t = threadIdx.x;
    const int w = t >> 5, l = t & 31;
    const int wm = w >> 2, wn = w & 3;
    const int q = blockIdx.x;
    const int z = q / nbz;
    const int y = q - z * nbz;
    const int row0 = blockIdx.y * 128;
    const int col0 = y * 128;

    float* C = (z == 0) ? C0 : (z == 1) ? C1 : C2;
    const float* bias = (z == 0) ? bias0 : (z == 1) ? bias1 : bias2;

    const __half* A_p = A + (size_t)row0 * K;
    size_t Boff = (size_t)q * 128 * K;
    const __half* B_h = Bth + Boff;
    const __half* B_l = Btl + Boff;

    const uint32_t aoff = (uint32_t)((wm * 64 + (l & 15)) * ROWB + (l >> 4) * 16);
    const uint32_t boff = (uint32_t)((wn * 32 + (l & 7) + ((l >> 4) & 1) * 8) * ROWB
                                     + ((l >> 3) & 1) * 16);

    float acc[4][4][4];
#pragma unroll
    for (int mt = 0; mt < 4; mt++)
#pragma unroll
        for (int nt = 0; nt < 4; nt++)
#pragma unroll
            for (int j = 0; j < 4; j++) acc[mt][nt][j] = 0.f;

    const int nch = K >> 5;
    load_stage(sb, 0, 0, A_p, B_h, B_l, K, t);

    for (int c = 0; c < nch; c++) {
        if (c + 1 < nch) {
            load_stage(sb, (c + 1) & 1, (c + 1) << 5, A_p, B_h, B_l, K, t);
            asm volatile("cp.async.wait_group 1;" ::: "memory");
        } else {
            asm volatile("cp.async.wait_group 0;" ::: "memory");
        }
        __syncthreads();

        uint32_t Abase = sb + (c & 1) * STAGEB;
        uint32_t Bhb = Abase + A_MAT;
        uint32_t Blb = Abase + 2 * A_MAT;
#pragma unroll
        for (int ks = 0; ks < 2; ks++) {
            uint32_t bh[2][4], bl[2][4];
#pragma unroll
            for (int p = 0; p < 2; p++) {
                ldsm4(bh[p], Bhb + boff + p * 1280 + ks * 32);
                ldsm4(bl[p], Blb + boff + p * 1280 + ks * 32);
            }
#pragma unroll
            for (int mt = 0; mt < 4; mt++) {
                uint32_t ah[4];
                ldsm4(ah, Abase + aoff + mt * 1280 + ks * 32);
#pragma unroll
                for (int nt = 0; nt < 4; nt++) {
                    float* cc = acc[mt][nt];
                    mma16816(cc, ah, &bh[nt >> 1][(nt & 1) * 2]);
                    mma16816(cc, ah, &bl[nt >> 1][(nt & 1) * 2]);
                }
            }
        }
        __syncthreads();
    }

    const int rl = l >> 2;
    const int cl = (l & 3) * 2;
#pragma unroll
    for (int mt = 0; mt < 4; mt++) {
#pragma unroll
        for (int rh = 0; rh < 2; rh++) {
            int r = row0 + wm * 64 + mt * 16 + rh * 8 + rl;
#pragma unroll
            for (int nt = 0; nt < 4; nt++) {
                int cix = col0 + wn * 32 + nt * 8 + cl;
                float v0 = acc[mt][nt][rh * 2 + 0];
                float v1 = acc[mt][nt][rh * 2 + 1];
                if (bias) { v0 += bias[cix]; v1 += bias[cix + 1]; }
                *(float2*)(C + (size_t)r * ldc + cix) = make_float2(v0, v1);
            }
        }
    }
}

// ---------------------------------------------------------------------------
// producers
// ---------------------------------------------------------------------------
__global__ void norm_split(const float* __restrict__ emb, __half* __restrict__ A) {
    int gw = (blockIdx.x * blockDim.x + threadIdx.x) >> 5;
    if (gw >= NODES) return;
    int lane = threadIdx.x & 31;
    float4 v = ((const float4*)(emb + (size_t)gw * EDIM))[lane];
    float ss = v.x * v.x + v.y * v.y + v.z * v.z + v.w * v.w;
#pragma unroll
    for (int o = 16; o > 0; o >>= 1) ss += __shfl_xor_sync(0xffffffffu, ss, o);
    float inv = 1.0f / fmaxf(sqrtf(ss), 1e-12f);
    size_t ui = ((size_t)gw * EDIM + lane * 4) >> 1;
    ((uint32_t*)A)[ui]     = pack_h2(v.x * inv, v.y * inv);
    ((uint32_t*)A)[ui + 1] = pack_h2(v.z * inv, v.w * inv);
}

// zero A pads: range [NODES*128, MPAD*256) halves on both arrays (covers K=128 & K=256 views)
__global__ void zero_pads_all() {
    size_t lo = (size_t)NODES * 128 / 2;            // uint32 units
    size_t n = (size_t)MPAD * 256 / 2 - lo;
    size_t i = (size_t)blockIdx.x * blockDim.x + threadIdx.x;
    if (i >= n) return;
    ((uint32_t*)g_A0)[lo + i] = 0;
    ((uint32_t*)g_A1)[lo + i] = 0;
}

// layer0 fused weights (fp32 compute): F_z = proj_w @ W0_z -> fp16 h/l, K-major.
// blocks 0..31 per z: weights (4 outputs/thread, coalesced float4 W loads);
// block 32: fused biases. Also zeroes BN stats (z0, block0).
__global__ void fuse_w(const float* __restrict__ proj_w, const float* __restrict__ proj_b,
                       const float* __restrict__ bases0, const float* __restrict__ root0,
                       const float* __restrict__ bias0) {
    int z = blockIdx.y;
    int t = threadIdx.x;
    const float* W = (z < 2) ? bases0 + (size_t)z * PDIM * HID : root0;
    if (z == 0 && blockIdx.x == 0) { g_sum[t] = 0.f; g_sumsq[t] = 0.f; }

    if (blockIdx.x == 32) {          // fused bias: one thread per output col
        float b = 0.f;
        for (int p = 0; p < PDIM; p++) b = fmaf(proj_b[p], W[(size_t)p * HID + t], b);
        if (z == 2) b += bias0[t];
        g_fbias[z * HID + t] = b;
        return;
    }

    int idx = blockIdx.x * 256 + t;  // 0..8191
    int e = idx >> 6;                // 0..127
    int o4 = (idx & 63) << 2;
    const float* pw = proj_w + (size_t)e * PDIM;
    float a0 = 0.f, a1 = 0.f, a2 = 0.f, a3 = 0.f;
    for (int p = 0; p < PDIM; p += 2) {
        float w0 = pw[p], w1 = pw[p + 1];
        float4 v0 = *(const float4*)&W[(size_t)p * HID + o4];
        float4 v1 = *(const float4*)&W[(size_t)(p + 1) * HID + o4];
        a0 = fmaf(w0, v0.x, fmaf(w1, v1.x, a0));
        a1 = fmaf(w0, v0.y, fmaf(w1, v1.y, a1));
        a2 = fmaf(w0, v0.z, fmaf(w1, v1.z, a2));
        a3 = fmaf(w0, v0.w, fmaf(w1, v1.w, a3));
    }
    float av[4] = {a0, a1, a2, a3};
#pragma unroll
    for (int j = 0; j < 4; j++) {
        __half h = __float2half_rn(av[j]);
        size_t off = ((size_t)(z * HID + o4 + j)) * EDIM + e;
        g_Bth[off] = h;
        g_Btl[off] = __float2half_rn(av[j] - __half2float(h));
    }
}

// layers 1,2 weights: transpose + split to fp16 h/l; zeroes BN stats.
__global__ void split_bt_layer(const float* __restrict__ bases, const float* __restrict__ root, int K) {
    int z = blockIdx.z;
    int idx = blockIdx.x * blockDim.x + threadIdx.x;
    if (z == 0 && blockIdx.x == 0 && threadIdx.x < HID) {
        g_sum[threadIdx.x] = 0.f;
        g_sumsq[threadIdx.x] = 0.f;
    }
    const float* in = (z < 2) ? bases + (size_t)z * K * HID : root;
    if (idx >= K * HID) return;
    int k = idx / HID, n = idx % HID;
    float v = in[idx];
    __half h = __float2half_rn(v);
    size_t o = ((size_t)z * HID + n) * K + k;
    g_Bth[o] = h;
    g_Btl[o] = __float2half_rn(v - __half2float(h));
}

// ---------------------------------------------------------------------------
// CSR build
// ---------------------------------------------------------------------------
__global__ void zero_counts() {
    int i = blockIdx.x * blockDim.x + threadIdx.x;
    if (i < NODES * NREL) g_cnt[i] = 0;
    if (i < NODES) { g_cntnode[i] = 0; g_fill[i] = 0; }
}
__global__ void count_edges(const int* __restrict__ dst, const int* __restrict__ et) {
    int e = blockIdx.x * blockDim.x + threadIdx.x;
    if (e < NEDGE) {
        int d = dst[e];
        atomicAdd(&g_cnt[d * NREL + et[e]], 1);
        atomicAdd(&g_cntnode[d], 1);
    }
}
__global__ void scan1() {
    __shared__ int sh[256];
    int t = threadIdx.x;
    int idx = blockIdx.x * 256 + t;
    int v = (idx < NODES) ? g_cntnode[idx] : 0;
    sh[t] = v;
    __syncthreads();
#pragma unroll
    for (int o = 1; o < 256; o <<= 1) {
        int x = (t >= o) ? sh[t - o] : 0;
        __syncthreads();
        sh[t] += x;
        __syncthreads();
    }
    if (idx < NODES) g_rowptr[idx + 1] = sh[t];
    if (t == 255) g_blksum[blockIdx.x] = sh[255];
}
__global__ void scan2() {
    int t = threadIdx.x;
    int carry = 0;
    for (int base = 0; base < SCANB; base += 32) {
        int idx = base + t;
        int vin = (idx < SCANB) ? g_blksum[idx] : 0;
        int v = vin;
#pragma unroll
        for (int o = 1; o < 32; o <<= 1) {
            int x = __shfl_up_sync(0xffffffffu, v, o);
            if (t >= o) v += x;
        }
        if (idx < SCANB) g_blksum[idx] = carry + v - vin;
        carry += __shfl_sync(0xffffffffu, v, 31);
    }
    if (t == 0) g_rowptr[0] = 0;
}
__global__ void scan3() {
    int idx = blockIdx.x * blockDim.x + threadIdx.x;
    if (idx < NODES) g_rowptr[idx + 1] += g_blksum[idx >> 8];
}
__global__ void scatter_edges(const int* __restrict__ src, const int* __restrict__ dst,
                              const int* __restrict__ et) {
    int e = blockIdx.x * blockDim.x + threadIdx.x;
    if (e >= NEDGE) return;
    int d = dst[e], r = et[e], s = src[e];
    int pos = g_rowptr[d] + atomicAdd(&g_fill[d], 1);
    g_packed[pos] = s | (r << 24);
    int c = g_cnt[d * NREL + r];
    g_invw[pos] = 1.0f / (float)(c > 0 ? c : 1);
}

// ---------------------------------------------------------------------------
// gather aggregation + fused BN statistics
// ---------------------------------------------------------------------------
#define AGG_BLOCKS 1184
__global__ void __launch_bounds__(256) csr_agg_bn(const float* __restrict__ comp) {
    __shared__ float s_sum[HID];
    __shared__ float s_sumsq[HID];
    __shared__ float s_comp[2 * NREL];
    int t = threadIdx.x;
    if (t < 2 * NREL) s_comp[t] = comp[t];
    s_sum[t] = 0.f;
    s_sumsq[t] = 0.f;
    __syncthreads();

    int lane = t & 31, wid = t >> 5;
    float bsum[8], bsq[8];
#pragma unroll
    for (int i = 0; i < 8; i++) { bsum[i] = 0.f; bsq[i] = 0.f; }

    for (int d = blockIdx.x * 8 + wid; d < NODES; d += AGG_BLOCKS * 8) {
        int beg = g_rowptr[d], end = g_rowptr[d + 1];
        float* bp = &g_buf[(size_t)d * HID];
        float4 acc0 = ((float4*)bp)[lane];
        float4 acc1 = ((float4*)bp)[lane + 32];
        for (int e = beg; e < end; e++) {
            int pk = __ldg(&g_packed[e]);
            float w = __ldg(&g_invw[e]);
            int s = pk & 0xFFFFFF;
            int r = pk >> 24;
            float c0 = s_comp[2 * r] * w;
            float c1 = s_comp[2 * r + 1] * w;
            const float4* h0p = (const float4*)&g_h0[(size_t)s * HID];
            const float4* h1p = (const float4*)&g_h1[(size_t)s * HID];
            float4 a0 = h0p[lane],      b0 = h1p[lane];
            float4 a1 = h0p[lane + 32], b1 = h1p[lane + 32];
            acc0.x += c0 * a0.x + c1 * b0.x;
            acc0.y += c0 * a0.y + c1 * b0.y;
            acc0.z += c0 * a0.z + c1 * b0.z;
            acc0.w += c0 * a0.w + c1 * b0.w;
            acc1.x += c0 * a1.x + c1 * b1.x;
            acc1.y += c0 * a1.y + c1 * b1.y;
            acc1.z += c0 * a1.z + c1 * b1.z;
            acc1.w += c0 * a1.w + c1 * b1.w;
        }
        ((float4*)bp)[lane] = acc0;
        ((float4*)bp)[lane + 32] = acc1;
        bsum[0] += acc0.x; bsq[0] += acc0.x * acc0.x;
        bsum[1] += acc0.y; bsq[1] += acc0.y * acc0.y;
        bsum[2] += acc0.z; bsq[2] += acc0.z * acc0.z;
        bsum[3] += acc0.w; bsq[3] += acc0.w * acc0.w;
        bsum[4] += acc1.x; bsq[4] += acc1.x * acc1.x;
        bsum[5] += acc1.y; bsq[5] += acc1.y * acc1.y;
        bsum[6] += acc1.z; bsq[6] += acc1.z * acc1.z;
        bsum[7] += acc1.w; bsq[7] += acc1.w * acc1.w;
    }

#pragma unroll
    for (int i = 0; i < 4; i++) {
        atomicAdd(&s_sum[lane * 4 + i], bsum[i]);
        atomicAdd(&s_sumsq[lane * 4 + i], bsq[i]);
        atomicAdd(&s_sum[128 + lane * 4 + i], bsum[4 + i]);
        atomicAdd(&s_sumsq[128 + lane * 4 + i], bsq[4 + i]);
    }
    __syncthreads();
    atomicAdd(&g_sum[t], s_sum[t]);
    atomicAdd(&g_sumsq[t], s_sumsq[t]);
}

// ---------------------------------------------------------------------------
// batchnorm finalize + apply
// ---------------------------------------------------------------------------
__global__ void bn_finalize(const float* __restrict__ gamma, const float* __restrict__ beta) {
    int c = threadIdx.x;
    const float invM = 1.0f / (float)NODES;
    float mean = g_sum[c] * invM;
    float var = g_sumsq[c] * invM - mean * mean;
    float sc = gamma[c] * rsqrtf(var + BN_EPS);
    g_scale[c] = sc;
    g_shift[c] = beta[c] - mean * sc;
}
__global__ void bn_apply_f32(float* __restrict__ out) {
    int idx = blockIdx.x * blockDim.x + threadIdx.x;
    if (idx >= NODES * HID / 4) return;
    int c4 = (idx & 63) << 2;
    float4 v = ((const float4*)g_buf)[idx];
    float4 sc = *(const float4*)&g_scale[c4];
    float4 sh = *(const float4*)&g_shift[c4];
    v.x = fmaxf(fmaf(v.x, sc.x, sh.x), 0.f);
    v.y = fmaxf(fmaf(v.y, sc.y, sh.y), 0.f);
    v.z = fmaxf(fmaf(v.z, sc.z, sh.z), 0.f);
    v.w = fmaxf(fmaf(v.w, sc.w, sh.w), 0.f);
    ((float4*)out)[idx] = v;
}
__global__ void bn_apply_half(__half* __restrict__ A) {
    int idx = blockIdx.x * blockDim.x + threadIdx.x;
    if (idx >= NODES * HID / 4) return;
    int c4 = (idx & 63) << 2;
    float4 v = ((const float4*)g_buf)[idx];
    float4 sc = *(const float4*)&g_scale[c4];
    float4 sh = *(const float4*)&g_shift[c4];
    v.x = fmaxf(fmaf(v.x, sc.x, sh.x), 0.f);
    v.y = fmaxf(fmaf(v.y, sc.y, sh.y), 0.f);
    v.z = fmaxf(fmaf(v.z, sc.z, sh.z), 0.f);
    v.w = fmaxf(fmaf(v.w, sc.w, sh.w), 0.f);
    ((uint32_t*)A)[idx * 2]     = pack_h2(v.x, v.y);
    ((uint32_t*)A)[idx * 2 + 1] = pack_h2(v.z, v.w);
}

// ---------------------------------------------------------------------------
// host launch
// ---------------------------------------------------------------------------
extern "C" void kernel_launch(void* const* d_in, const int* in_sizes, int n_in,
                              void* d_out, int out_size) {
    const int* edge_index = (const int*)d_in[0];
    const int* src = edge_index;
    const int* dst = edge_index + NEDGE;
    const int* etype = (const int*)d_in[1];
    const float* emb = (const float*)d_in[2];
    const float* proj_w = (const float*)d_in[3];
    const float* proj_b = (const float*)d_in[4];

    const float *comp[3], *bases[3], *root[3], *bias[3], *gamma[3], *beta[3];
    for (int l = 0; l < 3; l++) {
        comp[l]  = (const float*)d_in[5 + 6 * l];
        bases[l] = (const float*)d_in[6 + 6 * l];
        root[l]  = (const float*)d_in[7 + 6 * l];
        bias[l]  = (const float*)d_in[8 + 6 * l];
        gamma[l] = (const float*)d_in[9 + 6 * l];
        beta[l]  = (const float*)d_in[10 + 6 * l];
    }

    __half *A0, *A1, *Bth, *Btl;
    float *h0, *h1, *buf, *fbias;
    cudaGetSymbolAddress((void**)&A0, g_A0);
    cudaGetSymbolAddress((void**)&A1, g_A1);
    cudaGetSymbolAddress((void**)&Bth, g_Bth);
    cudaGetSymbolAddress((void**)&Btl, g_Btl);
    cudaGetSymbolAddress((void**)&h0, g_h0);
    cudaGetSymbolAddress((void**)&h1, g_h1);
    cudaGetSymbolAddress((void**)&buf, g_buf);
    cudaGetSymbolAddress((void**)&fbias, g_fbias);

    cudaFuncSetAttribute(gemm_mma, cudaFuncAttributeMaxDynamicSharedMemorySize, SMEM_GEMM);

    // producers
    norm_split<<<(NODES * 32 + 255) / 256, 256>>>(emb, A0);
    {
        size_t n = (size_t)MPAD * 256 / 2 - (size_t)NODES * 128 / 2;
        zero_pads_all<<<(int)((n + 255) / 256), 256>>>();
    }
    {
        dim3 g(33, 3);
        fuse_w<<<g, 256>>>(proj_w, proj_b, bases[0], root[0], bias[0]);
    }

    // launch 4: layer0 GEMM (ncu capture target), K=128
    {
        dim3 grid(6, MBLK);
        gemm_mma<<<grid, 256, SMEM_GEMM>>>(
            A0, EDIM, 2, Bth, Btl,
            h0, h1, buf, HID,
            fbias, fbias + HID, fbias + 2 * HID);
    }

    // CSR build
    zero_counts<<<(NODES * NREL + 255) / 256, 256>>>();
    count_edges<<<(NEDGE + 255) / 256, 256>>>(dst, etype);
    scan1<<<SCANB, 256>>>();
    scan2<<<1, 32>>>();
    scan3<<<(NODES + 255) / 256, 256>>>();
    scatter_edges<<<(NEDGE + 255) / 256, 256>>>(src, dst, etype);

    for (int l = 0; l < 3; l++) {
        if (l > 0) {
            dim3 g((HID * HID + 255) / 256, 1, 3);
            split_bt_layer<<<g, 256>>>(bases[l], root[l], HID);   // zeroes BN stats
            __half* A = (l == 1) ? A1 : A0;
            dim3 grid(6, MBLK);
            gemm_mma<<<grid, 256, SMEM_GEMM>>>(
                A, HID, 2, Bth, Btl,
                h0, h1, buf, HID,
                nullptr, nullptr, bias[l]);
        }
        csr_agg_bn<<<AGG_BLOCKS, 256>>>(comp[l]);
        bn_finalize<<<1, HID>>>(gamma[l], beta[l]);
        if (l < 2) {
            __half* oA = (l == 0) ? A1 : A0;
            bn_apply_half<<<(NODES * HID / 4 + 255) / 256, 256>>>(oA);
        } else {
            bn_apply_f32<<<(NODES * HID / 4 + 255) / 256, 256>>>((float*)d_out);
        }
    }
}

// round 15
// speedup vs baseline: 1.4198x; 1.1723x over previous
#include <cuda_runtime.h>
#include <cuda_fp16.h>
#include <cstdint>

#define NODES 50000
#define MPAD  50176          // 392 * 128
#define EDIM  128
#define PDIM  768
#define HID   256
#define NREL  16
#define NEDGE 400000
#define BN_EPS 1e-5f
#define MBLK  392            // MPAD / 128
#define SCANB 196
#define PADR  (MPAD - NODES)

// ---------------------------------------------------------------------------
// scratch (static device memory; no allocations)
// ---------------------------------------------------------------------------
__device__ __half g_A0[(size_t)MPAD * HID];     // x (fp16): layer0 xn K=128, layer2 input K=256
__device__ __half g_A1[(size_t)MPAD * HID];     // layer1 input K=256
__device__ __half g_Bth[3 * 256 * 768];          // B^T hi (K-major)
__device__ __half g_Btl[3 * 256 * 768];          // B^T lo
__device__ float g_fbias[3 * HID];
__device__ __half g_h0[(size_t)MPAD * HID];     // messages basis 0 (fp16)
__device__ __half g_h1[(size_t)MPAD * HID];     // messages basis 1 (fp16)
__device__ float g_buf[(size_t)MPAD * HID];
__device__ int   g_cnt[NODES * NREL];
__device__ int   g_cntnode[NODES];
__device__ int   g_fill[NODES];
__device__ int   g_rowptr[NODES + 1];
__device__ int   g_blksum[SCANB];
__device__ int   g_packed[NEDGE];
__device__ float g_invw[NEDGE];
__device__ float g_sum[HID], g_sumsq[HID], g_scale[HID], g_shift[HID];

// ---------------------------------------------------------------------------
// helpers
// ---------------------------------------------------------------------------
__device__ __forceinline__ uint32_t smem_u32(const void* p) {
    uint32_t a;
    asm("{ .reg .u64 t; cvta.to.shared.u64 t, %1; cvt.u32.u64 %0, t; }" : "=r"(a) : "l"(p));
    return a;
}
__device__ __forceinline__ void cp16(uint32_t dst, const void* src) {
    asm volatile("cp.async.cg.shared.global [%0], [%1], 16;" :: "r"(dst), "l"(src) : "memory");
}
__device__ __forceinline__ void ldsm4(uint32_t* r, uint32_t addr) {
    asm volatile("ldmatrix.sync.aligned.m8n8.x4.shared.b16 {%0,%1,%2,%3}, [%4];"
                 : "=r"(r[0]), "=r"(r[1]), "=r"(r[2]), "=r"(r[3]) : "r"(addr));
}
__device__ __forceinline__ void mma16816(float* c, const uint32_t* a, const uint32_t* b) {
    asm volatile("mma.sync.aligned.m16n8k16.row.col.f32.f16.f16.f32 "
                 "{%0,%1,%2,%3}, {%4,%5,%6,%7}, {%8,%9}, {%0,%1,%2,%3};"
                 : "+f"(c[0]), "+f"(c[1]), "+f"(c[2]), "+f"(c[3])
                 : "r"(a[0]), "r"(a[1]), "r"(a[2]), "r"(a[3]), "r"(b[0]), "r"(b[1]));
}
static __device__ __forceinline__ uint32_t pack_h2(float a, float b) {
    __half2 t;
    t.x = __float2half_rn(a);
    t.y = __float2half_rn(b);
    return *reinterpret_cast<uint32_t*>(&t);
}

// chunk-32 layout: 64B rows padded to 80B. stage = A(128x80) | Bh(128x80) | Bl(128x80)
#define ROWB    80
#define A_MAT   10240
#define STAGEB  30720
#define SMEM_GEMM (2 * STAGEB)   // 61440 -> 2 CTAs/SM

// ---------------------------------------------------------------------------
// fp16 2-term GEMM via mma.sync: out_z = A @ (Bh+Bl)_z^T (+bias_z)
// z<2 -> fp16 message arrays H0/H1; z==2 -> f32 buf.
// CTA tile 128x128, 256 threads (2x4 warps), warp tile 64x32, K-chunk 32,
// 2-stage cp.async, 2 CTAs/SM. blockIdx.x = output tile (A reuse), .y = rows.
// ---------------------------------------------------------------------------
__device__ __forceinline__ void load_stage(
    uint32_t sb, int stage, int k0,
    const __half* __restrict__ A,
    const __half* __restrict__ Bh, const __half* __restrict__ Bl,
    int K, int t)
{
    uint32_t base = sb + stage * STAGEB;
#pragma unroll
    for (int i = 0; i < 2; i++) {
        int unit = t + i * 256;
        int r = unit >> 2, u = unit & 3;
        uint32_t off = r * ROWB + u * 16;
        cp16(base + off, A + (size_t)r * K + k0 + u * 8);
    }
#pragma unroll
    for (int i = 0; i < 2; i++) {
        int unit = t + i * 256;
        int r = unit >> 2, u = unit & 3;
        uint32_t off = r * ROWB + u * 16;
        cp16(base + A_MAT + off,     Bh + (size_t)r * K + k0 + u * 8);
        cp16(base + 2 * A_MAT + off, Bl + (size_t)r * K + k0 + u * 8);
    }
    asm volatile("cp.async.commit_group;" ::: "memory");
}

__global__ void __launch_bounds__(256, 2) gemm_mma(
    const __half* __restrict__ A, int K, int nbz,
    const __half* __restrict__ Bth, const __half* __restrict__ Btl,
    __half* H0, __half* H1, float* Cbuf, int ldc,
    const float* bias0, const float* bias1, const float* bias2)
{
    extern __shared__ char smem[];
    uint32_t sb = smem_u32(smem);
    const int t = threadIdx.x;
    const int w = t >> 5, l = t & 31;
    const int wm = w >> 2, wn = w & 3;
    const int q = blockIdx.x;
    const int z = q / nbz;
    const int y = q - z * nbz;
    const int row0 = blockIdx.y * 128;
    const int col0 = y * 128;

    const float* bias = (z == 0) ? bias0 : (z == 1) ? bias1 : bias2;

    const __half* A_p = A + (size_t)row0 * K;
    size_t Boff = (size_t)q * 128 * K;
    const __half* B_h = Bth + Boff;
    const __half* B_l = Btl + Boff;

    const uint32_t aoff = (uint32_t)((wm * 64 + (l & 15)) * ROWB + (l >> 4) * 16);
    const uint32_t boff = (uint32_t)((wn * 32 + (l & 7) + ((l >> 4) & 1) * 8) * ROWB
                                     + ((l >> 3) & 1) * 16);

    float acc[4][4][4];
#pragma unroll
    for (int mt = 0; mt < 4; mt++)
#pragma unroll
        for (int nt = 0; nt < 4; nt++)
#pragma unroll
            for (int j = 0; j < 4; j++) acc[mt][nt][j] = 0.f;

    const int nch = K >> 5;
    load_stage(sb, 0, 0, A_p, B_h, B_l, K, t);

    for (int c = 0; c < nch; c++) {
        if (c + 1 < nch) {
            load_stage(sb, (c + 1) & 1, (c + 1) << 5, A_p, B_h, B_l, K, t);
            asm volatile("cp.async.wait_group 1;" ::: "memory");
        } else {
            asm volatile("cp.async.wait_group 0;" ::: "memory");
        }
        __syncthreads();

        uint32_t Abase = sb + (c & 1) * STAGEB;
        uint32_t Bhb = Abase + A_MAT;
        uint32_t Blb = Abase + 2 * A_MAT;
#pragma unroll
        for (int ks = 0; ks < 2; ks++) {
            uint32_t bh[2][4], bl[2][4];
#pragma unroll
            for (int p = 0; p < 2; p++) {
                ldsm4(bh[p], Bhb + boff + p * 1280 + ks * 32);
                ldsm4(bl[p], Blb + boff + p * 1280 + ks * 32);
            }
#pragma unroll
            for (int mt = 0; mt < 4; mt++) {
                uint32_t ah[4];
                ldsm4(ah, Abase + aoff + mt * 1280 + ks * 32);
#pragma unroll
                for (int nt = 0; nt < 4; nt++) {
                    float* cc = acc[mt][nt];
                    mma16816(cc, ah, &bh[nt >> 1][(nt & 1) * 2]);
                    mma16816(cc, ah, &bl[nt >> 1][(nt & 1) * 2]);
                }
            }
        }
        __syncthreads();
    }

    const int rl = l >> 2;
    const int cl = (l & 3) * 2;
    __half* H = (z == 0) ? H0 : H1;
#pragma unroll
    for (int mt = 0; mt < 4; mt++) {
#pragma unroll
        for (int rh = 0; rh < 2; rh++) {
            int r = row0 + wm * 64 + mt * 16 + rh * 8 + rl;
#pragma unroll
            for (int nt = 0; nt < 4; nt++) {
                int cix = col0 + wn * 32 + nt * 8 + cl;
                float v0 = acc[mt][nt][rh * 2 + 0];
                float v1 = acc[mt][nt][rh * 2 + 1];
                if (bias) { v0 += bias[cix]; v1 += bias[cix + 1]; }
                if (z == 2) {
                    *(float2*)(Cbuf + (size_t)r * ldc + cix) = make_float2(v0, v1);
                } else {
                    ((uint32_t*)H)[((size_t)r * ldc + cix) >> 1] = pack_h2(v0, v1);
                }
            }
        }
    }
}

// ---------------------------------------------------------------------------
// producers
// ---------------------------------------------------------------------------
__global__ void norm_split(const float* __restrict__ emb, __half* __restrict__ A) {
    int gw = (blockIdx.x * blockDim.x + threadIdx.x) >> 5;
    if (gw >= NODES) return;
    int lane = threadIdx.x & 31;
    float4 v = ((const float4*)(emb + (size_t)gw * EDIM))[lane];
    float ss = v.x * v.x + v.y * v.y + v.z * v.z + v.w * v.w;
#pragma unroll
    for (int o = 16; o > 0; o >>= 1) ss += __shfl_xor_sync(0xffffffffu, ss, o);
    float inv = 1.0f / fmaxf(sqrtf(ss), 1e-12f);
    size_t ui = ((size_t)gw * EDIM + lane * 4) >> 1;
    ((uint32_t*)A)[ui]     = pack_h2(v.x * inv, v.y * inv);
    ((uint32_t*)A)[ui + 1] = pack_h2(v.z * inv, v.w * inv);
}

__global__ void zero_pads_all() {
    size_t lo = (size_t)NODES * 128 / 2;
    size_t n = (size_t)MPAD * 256 / 2 - lo;
    size_t i = (size_t)blockIdx.x * blockDim.x + threadIdx.x;
    if (i >= n) return;
    ((uint32_t*)g_A0)[lo + i] = 0;
    ((uint32_t*)g_A1)[lo + i] = 0;
}

// layer0 fused weights (fp32): F_z = proj_w @ W0_z -> fp16 h/l, K-major; fbias.
__global__ void fuse_w(const float* __restrict__ proj_w, const float* __restrict__ proj_b,
                       const float* __restrict__ bases0, const float* __restrict__ root0,
                       const float* __restrict__ bias0) {
    int z = blockIdx.y;
    int t = threadIdx.x;
    const float* W = (z < 2) ? bases0 + (size_t)z * PDIM * HID : root0;
    if (z == 0 && blockIdx.x == 0) { g_sum[t] = 0.f; g_sumsq[t] = 0.f; }

    if (blockIdx.x == 32) {
        float b = 0.f;
        for (int p = 0; p < PDIM; p++) b = fmaf(proj_b[p], W[(size_t)p * HID + t], b);
        if (z == 2) b += bias0[t];
        g_fbias[z * HID + t] = b;
        return;
    }

    int idx = blockIdx.x * 256 + t;
    int e = idx >> 6;
    int o4 = (idx & 63) << 2;
    const float* pw = proj_w + (size_t)e * PDIM;
    float a0 = 0.f, a1 = 0.f, a2 = 0.f, a3 = 0.f;
    for (int p = 0; p < PDIM; p += 2) {
        float w0 = pw[p], w1 = pw[p + 1];
        float4 v0 = *(const float4*)&W[(size_t)p * HID + o4];
        float4 v1 = *(const float4*)&W[(size_t)(p + 1) * HID + o4];
        a0 = fmaf(w0, v0.x, fmaf(w1, v1.x, a0));
        a1 = fmaf(w0, v0.y, fmaf(w1, v1.y, a1));
        a2 = fmaf(w0, v0.z, fmaf(w1, v1.z, a2));
        a3 = fmaf(w0, v0.w, fmaf(w1, v1.w, a3));
    }
    float av[4] = {a0, a1, a2, a3};
#pragma unroll
    for (int j = 0; j < 4; j++) {
        __half h = __float2half_rn(av[j]);
        size_t off = ((size_t)(z * HID + o4 + j)) * EDIM + e;
        g_Bth[off] = h;
        g_Btl[off] = __float2half_rn(av[j] - __half2float(h));
    }
}

__global__ void split_bt_layer(const float* __restrict__ bases, const float* __restrict__ root, int K) {
    int z = blockIdx.z;
    int idx = blockIdx.x * blockDim.x + threadIdx.x;
    if (z == 0 && blockIdx.x == 0 && threadIdx.x < HID) {
        g_sum[threadIdx.x] = 0.f;
        g_sumsq[threadIdx.x] = 0.f;
    }
    const float* in = (z < 2) ? bases + (size_t)z * K * HID : root;
    if (idx >= K * HID) return;
    int k = idx / HID, n = idx % HID;
    float v = in[idx];
    __half h = __float2half_rn(v);
    size_t o = ((size_t)z * HID + n) * K + k;
    g_Bth[o] = h;
    g_Btl[o] = __float2half_rn(v - __half2float(h));
}

// ---------------------------------------------------------------------------
// CSR build
// ---------------------------------------------------------------------------
__global__ void zero_counts() {
    int i = blockIdx.x * blockDim.x + threadIdx.x;
    if (i < NODES * NREL) g_cnt[i] = 0;
    if (i < NODES) { g_cntnode[i] = 0; g_fill[i] = 0; }
}
__global__ void count_edges(const int* __restrict__ dst, const int* __restrict__ et) {
    int e = blockIdx.x * blockDim.x + threadIdx.x;
    if (e < NEDGE) {
        int d = dst[e];
        atomicAdd(&g_cnt[d * NREL + et[e]], 1);
        atomicAdd(&g_cntnode[d], 1);
    }
}
__global__ void scan1() {
    __shared__ int sh[256];
    int t = threadIdx.x;
    int idx = blockIdx.x * 256 + t;
    int v = (idx < NODES) ? g_cntnode[idx] : 0;
    sh[t] = v;
    __syncthreads();
#pragma unroll
    for (int o = 1; o < 256; o <<= 1) {
        int x = (t >= o) ? sh[t - o] : 0;
        __syncthreads();
        sh[t] += x;
        __syncthreads();
    }
    if (idx < NODES) g_rowptr[idx + 1] = sh[t];
    if (t == 255) g_blksum[blockIdx.x] = sh[255];
}
__global__ void scan2() {
    int t = threadIdx.x;
    int carry = 0;
    for (int base = 0; base < SCANB; base += 32) {
        int idx = base + t;
        int vin = (idx < SCANB) ? g_blksum[idx] : 0;
        int v = vin;
#pragma unroll
        for (int o = 1; o < 32; o <<= 1) {
            int x = __shfl_up_sync(0xffffffffu, v, o);
            if (t >= o) v += x;
        }
        if (idx < SCANB) g_blksum[idx] = carry + v - vin;
        carry += __shfl_sync(0xffffffffu, v, 31);
    }
    if (t == 0) g_rowptr[0] = 0;
}
__global__ void scan3() {
    int idx = blockIdx.x * blockDim.x + threadIdx.x;
    if (idx < NODES) g_rowptr[idx + 1] += g_blksum[idx >> 8];
}
__global__ void scatter_edges(const int* __restrict__ src, const int* __restrict__ dst,
                              const int* __restrict__ et) {
    int e = blockIdx.x * blockDim.x + threadIdx.x;
    if (e >= NEDGE) return;
    int d = dst[e], r = et[e], s = src[e];
    int pos = g_rowptr[d] + atomicAdd(&g_fill[d], 1);
    g_packed[pos] = s | (r << 24);
    int c = g_cnt[d * NREL + r];
    g_invw[pos] = 1.0f / (float)(c > 0 ? c : 1);
}

// ---------------------------------------------------------------------------
// gather aggregation (fp16 messages) + fused BN statistics
// ---------------------------------------------------------------------------
#define AGG_BLOCKS 1184
__global__ void __launch_bounds__(256) csr_agg_bn(const float* __restrict__ comp) {
    __shared__ float s_sum[HID];
    __shared__ float s_sumsq[HID];
    __shared__ float s_comp[2 * NREL];
    int t = threadIdx.x;
    if (t < 2 * NREL) s_comp[t] = comp[t];
    s_sum[t] = 0.f;
    s_sumsq[t] = 0.f;
    __syncthreads();

    int lane = t & 31, wid = t >> 5;
    float bsum[8], bsq[8];
#pragma unroll
    for (int i = 0; i < 8; i++) { bsum[i] = 0.f; bsq[i] = 0.f; }

    for (int d = blockIdx.x * 8 + wid; d < NODES; d += AGG_BLOCKS * 8) {
        int beg = g_rowptr[d], end = g_rowptr[d + 1];
        float* bp = &g_buf[(size_t)d * HID];
        float4 acc0 = ((float4*)bp)[lane];
        float4 acc1 = ((float4*)bp)[lane + 32];
        for (int e = beg; e < end; e++) {
            int pk = __ldg(&g_packed[e]);
            float w = __ldg(&g_invw[e]);
            int s = pk & 0xFFFFFF;
            int r = pk >> 24;
            float c0 = s_comp[2 * r] * w;
            float c1 = s_comp[2 * r + 1] * w;
            const uint2* p0 = (const uint2*)(g_h0 + (size_t)s * HID);
            const uint2* p1 = (const uint2*)(g_h1 + (size_t)s * HID);
            uint2 u00 = p0[lane], u01 = p0[lane + 32];
            uint2 u10 = p1[lane], u11 = p1[lane + 32];
            float2 a0a = __half22float2(*(__half2*)&u00.x);
            float2 a0b = __half22float2(*(__half2*)&u00.y);
            float2 a1a = __half22float2(*(__half2*)&u01.x);
            float2 a1b = __half22float2(*(__half2*)&u01.y);
            float2 b0a = __half22float2(*(__half2*)&u10.x);
            float2 b0b = __half22float2(*(__half2*)&u10.y);
            float2 b1a = __half22float2(*(__half2*)&u11.x);
            float2 b1b = __half22float2(*(__half2*)&u11.y);
            acc0.x += c0 * a0a.x + c1 * b0a.x;
            acc0.y += c0 * a0a.y + c1 * b0a.y;
            acc0.z += c0 * a0b.x + c1 * b0b.x;
            acc0.w += c0 * a0b.y + c1 * b0b.y;
            acc1.x += c0 * a1a.x + c1 * b1a.x;
            acc1.y += c0 * a1a.y + c1 * b1a.y;
            acc1.z += c0 * a1b.x + c1 * b1b.x;
            acc1.w += c0 * a1b.y + c1 * b1b.y;
        }
        ((float4*)bp)[lane] = acc0;
        ((float4*)bp)[lane + 32] = acc1;
        bsum[0] += acc0.x; bsq[0] += acc0.x * acc0.x;
        bsum[1] += acc0.y; bsq[1] += acc0.y * acc0.y;
        bsum[2] += acc0.z; bsq[2] += acc0.z * acc0.z;
        bsum[3] += acc0.w; bsq[3] += acc0.w * acc0.w;
        bsum[4] += acc1.x; bsq[4] += acc1.x * acc1.x;
        bsum[5] += acc1.y; bsq[5] += acc1.y * acc1.y;
        bsum[6] += acc1.z; bsq[6] += acc1.z * acc1.z;
        bsum[7] += acc1.w; bsq[7] += acc1.w * acc1.w;
    }

#pragma unroll
    for (int i = 0; i < 4; i++) {
        atomicAdd(&s_sum[lane * 4 + i], bsum[i]);
        atomicAdd(&s_sumsq[lane * 4 + i], bsq[i]);
        atomicAdd(&s_sum[128 + lane * 4 + i], bsum[4 + i]);
        atomicAdd(&s_sumsq[128 + lane * 4 + i], bsq[4 + i]);
    }
    __syncthreads();
    atomicAdd(&g_sum[t], s_sum[t]);
    atomicAdd(&g_sumsq[t], s_sumsq[t]);
}

// ---------------------------------------------------------------------------
// batchnorm finalize + apply
// ---------------------------------------------------------------------------
__global__ void bn_finalize(const float* __restrict__ gamma, const float* __restrict__ beta) {
    int c = threadIdx.x;
    const float invM = 1.0f / (float)NODES;
    float mean = g_sum[c] * invM;
    float var = g_sumsq[c] * invM - mean * mean;
    float sc = gamma[c] * rsqrtf(var + BN_EPS);
    g_scale[c] = sc;
    g_shift[c] = beta[c] - mean * sc;
}
__global__ void bn_apply_f32(float* __restrict__ out) {
    int idx = blockIdx.x * blockDim.x + threadIdx.x;
    if (idx >= NODES * HID / 4) return;
    int c4 = (idx & 63) << 2;
    float4 v = ((const float4*)g_buf)[idx];
    float4 sc = *(const float4*)&g_scale[c4];
    float4 sh = *(const float4*)&g_shift[c4];
    v.x = fmaxf(fmaf(v.x, sc.x, sh.x), 0.f);
    v.y = fmaxf(fmaf(v.y, sc.y, sh.y), 0.f);
    v.z = fmaxf(fmaf(v.z, sc.z, sh.z), 0.f);
    v.w = fmaxf(fmaf(v.w, sc.w, sh.w), 0.f);
    ((float4*)out)[idx] = v;
}
__global__ void bn_apply_half(__half* __restrict__ A) {
    int idx = blockIdx.x * blockDim.x + threadIdx.x;
    if (idx >= NODES * HID / 4) return;
    int c4 = (idx & 63) << 2;
    float4 v = ((const float4*)g_buf)[idx];
    float4 sc = *(const float4*)&g_scale[c4];
    float4 sh = *(const float4*)&g_shift[c4];
    v.x = fmaxf(fmaf(v.x, sc.x, sh.x), 0.f);
    v.y = fmaxf(fmaf(v.y, sc.y, sh.y), 0.f);
    v.z = fmaxf(fmaf(v.z, sc.z, sh.z), 0.f);
    v.w = fmaxf(fmaf(v.w, sc.w, sh.w), 0.f);
    ((uint32_t*)A)[idx * 2]     = pack_h2(v.x, v.y);
    ((uint32_t*)A)[idx * 2 + 1] = pack_h2(v.z, v.w);
}

// ---------------------------------------------------------------------------
// host launch
// ---------------------------------------------------------------------------
extern "C" void kernel_launch(void* const* d_in, const int* in_sizes, int n_in,
                              void* d_out, int out_size) {
    const int* edge_index = (const int*)d_in[0];
    const int* src = edge_index;
    const int* dst = edge_index + NEDGE;
    const int* etype = (const int*)d_in[1];
    const float* emb = (const float*)d_in[2];
    const float* proj_w = (const float*)d_in[3];
    const float* proj_b = (const float*)d_in[4];

    const float *comp[3], *bases[3], *root[3], *bias[3], *gamma[3], *beta[3];
    for (int l = 0; l < 3; l++) {
        comp[l]  = (const float*)d_in[5 + 6 * l];
        bases[l] = (const float*)d_in[6 + 6 * l];
        root[l]  = (const float*)d_in[7 + 6 * l];
        bias[l]  = (const float*)d_in[8 + 6 * l];
        gamma[l] = (const float*)d_in[9 + 6 * l];
        beta[l]  = (const float*)d_in[10 + 6 * l];
    }

    __half *A0, *A1, *Bth, *Btl, *h0, *h1;
    float *buf, *fbias;
    cudaGetSymbolAddress((void**)&A0, g_A0);
    cudaGetSymbolAddress((void**)&A1, g_A1);
    cudaGetSymbolAddress((void**)&Bth, g_Bth);
    cudaGetSymbolAddress((void**)&Btl, g_Btl);
    cudaGetSymbolAddress((void**)&h0, g_h0);
    cudaGetSymbolAddress((void**)&h1, g_h1);
    cudaGetSymbolAddress((void**)&buf, g_buf);
    cudaGetSymbolAddress((void**)&fbias, g_fbias);

    cudaFuncSetAttribute(gemm_mma, cudaFuncAttributeMaxDynamicSharedMemorySize, SMEM_GEMM);

    // producers
    norm_split<<<(NODES * 32 + 255) / 256, 256>>>(emb, A0);
    {
        size_t n = (size_t)MPAD * 256 / 2 - (size_t)NODES * 128 / 2;
        zero_pads_all<<<(int)((n + 255) / 256), 256>>>();
    }
    {
        dim3 g(33, 3);
        fuse_w<<<g, 256>>>(proj_w, proj_b, bases[0], root[0], bias[0]);
    }

    // launch 4: layer0 GEMM (ncu capture target), K=128
    {
        dim3 grid(6, MBLK);
        gemm_mma<<<grid, 256, SMEM_GEMM>>>(
            A0, EDIM, 2, Bth, Btl,
            h0, h1, buf, HID,
            fbias, fbias + HID, fbias + 2 * HID);
    }

    // CSR build
    zero_counts<<<(NODES * NREL + 255) / 256, 256>>>();
    count_edges<<<(NEDGE + 255) / 256, 256>>>(dst, etype);
    scan1<<<SCANB, 256>>>();
    scan2<<<1, 32>>>();
    scan3<<<(NODES + 255) / 256, 256>>>();
    scatter_edges<<<(NEDGE + 255) / 256, 256>>>(src, dst, etype);

    for (int l = 0; l < 3; l++) {
        if (l > 0) {
            dim3 g((HID * HID + 255) / 256, 1, 3);
            split_bt_layer<<<g, 256>>>(bases[l], root[l], HID);   // zeroes BN stats
            __half* A = (l == 1) ? A1 : A0;
            dim3 grid(6, MBLK);
            gemm_mma<<<grid, 256, SMEM_GEMM>>>(
                A, HID, 2, Bth, Btl,
                h0, h1, buf, HID,
                nullptr, nullptr, bias[l]);
        }
        csr_agg_bn<<<AGG_BLOCKS, 256>>>(comp[l]);
        bn_finalize<<<1, HID>>>(gamma[l], beta[l]);
        if (l < 2) {
            __half* oA = (l == 0) ? A1 : A0;
            bn_apply_half<<<(NODES * HID / 4 + 255) / 256, 256>>>(oA);
        } else {
            bn_apply_f32<<<(NODES * HID / 4 + 255) / 256, 256>>>((float*)d_out);
        }
    }
}